// round 12
// baseline (speedup 1.0000x reference)
#include <cuda_runtime.h>
#include <cuda_bf16.h>
#include <mma.h>
#include <math.h>
#include <stdint.h>

using namespace nvcuda;

#define NB 4
#define NT 4096
#define ND 256

#define BM 128
#define BN 128
#define BK 32
#define NTILES_M (NT / BM)      // 32
#define N_ITEMS 1024            // 32 ti * 4 b * 2 nh * 4 seg (some skipped)

#define LDAF 36                 // smem row stride (f32 elems): 32 + 4 pad = 144B
#define LDE 136                 // epilogue f32 row stride

__device__ __align__(16) float g_dinv[NB * NT];
__device__ unsigned int g_rmax[NB * NT];         // zero-init; atomicMax idempotent
__device__ int g_ctr;
__device__ __align__(16) float g_Atf[(size_t)NB * NT * NT];    // scaled+masked, tf32-rounded
__device__ __align__(16) float g_Ktf[(size_t)NB * ND * NT];    // [b][d][s], tf32-rounded
__device__ __align__(16) float g_part[(size_t)N_ITEMS * BM * BN];  // 64MB partials

#define SG 0.70710678118654752440f
#define GATE_TH 7.0710678118654752e-10f          // 1e-9 * sqrt(0.5)

#define TILE_F  (128 * LDAF * 4)                 // 18432 bytes per operand tile
#define STAGE_F (2 * TILE_F)                     // 36864 (A + B)
#define SM_TOTAL (3 * STAGE_F)                   // 110592

static __device__ __forceinline__ uint32_t smem_u32(const void* p) {
    uint32_t a;
    asm("{ .reg .u64 t; cvta.to.shared.u64 t, %1; cvt.u32.u64 %0, t; }" : "=r"(a) : "l"(p));
    return a;
}
static __device__ __forceinline__ void cp16(uint32_t dst, const void* src) {
    asm volatile("cp.async.cg.shared.global [%0], [%1], 16;" :: "r"(dst), "l"(src));
}
static __device__ __forceinline__ float to_tf32(float v) {
    float o;
    asm("cvt.rna.tf32.f32 %0, %1;" : "=f"(o) : "f"(v));
    return o;
}

// ---------------------------------------------------------------------------
__global__ void reset_kernel() { if (threadIdx.x == 0) g_ctr = 0; }

// ---------------------------------------------------------------------------
// Kernel 1: rowsum -> dinv   (at HBM roofline)
// ---------------------------------------------------------------------------
__global__ __launch_bounds__(256) void rowsum_kernel(const float* __restrict__ A)
{
    int row = blockIdx.x;
    const float4* a4 = reinterpret_cast<const float4*>(A + (size_t)row * NT);
    float s = 0.f;
    #pragma unroll
    for (int i = 0; i < NT / 4 / 256; i++) {
        float4 v = a4[threadIdx.x + i * 256];
        s += (v.x + v.y) + (v.z + v.w);
    }
    #pragma unroll
    for (int o = 16; o > 0; o >>= 1) s += __shfl_xor_sync(0xffffffffu, s, o);
    __shared__ float ws[8];
    int lane = threadIdx.x & 31, w = threadIdx.x >> 5;
    if (lane == 0) ws[w] = s;
    __syncthreads();
    if (threadIdx.x == 0) {
        float tot = ws[0];
        #pragma unroll
        for (int i = 1; i < 8; i++) tot += ws[i];
        g_dinv[row] = 1.0f / sqrtf(tot + 1e-6f);
    }
}

// ---------------------------------------------------------------------------
// Kernel 2: K[b][s][d] -> Ktf[b][d][s] f32 (tf32-rounded) transpose
// ---------------------------------------------------------------------------
__global__ __launch_bounds__(256) void kt_kernel(const float* __restrict__ K)
{
    __shared__ float tile[32][33];
    int s0 = blockIdx.x * 32, d0 = blockIdx.y * 32, b = blockIdx.z;
    const float* Kb = K + (size_t)b * NT * ND;
    int tid = threadIdx.x;
    #pragma unroll
    for (int q = 0; q < 4; q++) {
        int idx = tid + q * 256;
        int r = idx >> 5, c = idx & 31;
        tile[r][c] = Kb[(size_t)(s0 + r) * ND + d0 + c];
    }
    __syncthreads();
    #pragma unroll
    for (int q = 0; q < 4; q++) {
        int idx = tid + q * 256;
        int dr = idx >> 5, sc = idx & 31;
        g_Ktf[(size_t)b * ND * NT + (size_t)(d0 + dr) * NT + s0 + sc] =
            to_tf32(tile[sc][dr]);
    }
}

// ---------------------------------------------------------------------------
// Kernel 3: convert lower-triangle A -> scaled/masked tf32-rounded f32 + rmax.
// Pair-interleaved: thread (2k+h) handles elems [q*16+h*8, +8) of row k.
// ---------------------------------------------------------------------------
__global__ __launch_bounds__(256) void convert_kernel(const float* __restrict__ A)
{
    int ci = blockIdx.x, ti = blockIdx.y, b = blockIdx.z;
    if (ci > ti) return;
    int t0 = ti * 128, s0 = ci * 128;
    int tid = threadIdx.x;
    int r = tid >> 1;
    int h = tid & 1;
    int t = t0 + r;

    const float* dinv = g_dinv + b * NT;
    float dt = SG * __ldg(dinv + t);
    const float* Arow = A + (size_t)b * NT * NT + (size_t)t * NT + s0;
    float* Adst = g_Atf + ((size_t)b * NT + t) * NT + s0;

    bool diag = (ci == ti);
    float rmax = 0.f;
    #pragma unroll
    for (int q = 0; q < 8; q++) {
        int e0 = q * 16 + h * 8;
        float4 a0 = *reinterpret_cast<const float4*>(Arow + e0);
        float4 a1 = *reinterpret_cast<const float4*>(Arow + e0 + 4);
        float4 d0 = __ldg(reinterpret_cast<const float4*>(dinv + s0 + e0));
        float4 d1 = __ldg(reinterpret_cast<const float4*>(dinv + s0 + e0 + 4));
        float v[8] = { dt * a0.x * d0.x, dt * a0.y * d0.y, dt * a0.z * d0.z, dt * a0.w * d0.w,
                       dt * a1.x * d1.x, dt * a1.y * d1.y, dt * a1.z * d1.z, dt * a1.w * d1.w };
        int sbase = s0 + e0;
        #pragma unroll
        for (int e = 0; e < 8; e++) {
            if (diag && (sbase + e > t)) v[e] = 0.f;
            rmax = fmaxf(rmax, fabsf(v[e]));
            v[e] = to_tf32(v[e]);
        }
        *reinterpret_cast<float4*>(Adst + e0)     = make_float4(v[0], v[1], v[2], v[3]);
        *reinterpret_cast<float4*>(Adst + e0 + 4) = make_float4(v[4], v[5], v[6], v[7]);
    }
    rmax = fmaxf(rmax, __shfl_xor_sync(0xffffffffu, rmax, 1));
    if (h == 0)
        atomicMax(&g_rmax[b * NT + t], __float_as_uint(rmax));
}

// ---------------------------------------------------------------------------
// Kernel 4: persistent split-K tf32 WMMA GEMM, 3-stage cp.async pipeline.
// __launch_bounds__(256,2) caps regs at 128 -> genuinely 2 CTAs/SM.
// ---------------------------------------------------------------------------
__global__ __launch_bounds__(256, 2) void causal_mm_wmma()
{
    extern __shared__ char smem[];
    uint32_t sb = smem_u32(smem);
    __shared__ int s_item;

    int tid = threadIdx.x, wid = tid >> 5;
    int wm = wid & 3;
    int wn = wid >> 2;
    int lr = tid >> 1;
    int lb = (tid & 1) * 64;           // byte offset within 128B row payload

    while (true) {
        if (tid == 0) s_item = atomicAdd(&g_ctr, 1);
        __syncthreads();
        int item = s_item;
        if (item >= N_ITEMS) break;

        int ti  = NTILES_M - 1 - (item >> 5);   // big tiles first
        int rem = item & 31;
        int b   = rem >> 3;
        int nh  = (rem >> 2) & 1;
        int seg = rem & 3;
        int nK  = 4 * (ti + 1);
        int ns  = (ti + 8) >> 3;                // ceil((ti+1)/8)
        if (seg >= ns) continue;
        int c0 = seg * 32;
        int c1 = min(c0 + 32, nK);

        int t0  = ti * BM;
        int cn0 = nh * BN;
        const float* Ag = g_Atf + ((size_t)b * NT + t0) * NT;
        const float* Bg = g_Ktf + ((size_t)b * ND + cn0) * NT;

        wmma::fragment<wmma::accumulator, 16, 16, 8, float> facc[2][4];
        #pragma unroll
        for (int i = 0; i < 2; i++)
            #pragma unroll
            for (int j = 0; j < 4; j++) wmma::fill_fragment(facc[i][j], 0.0f);

        auto load_stage = [&](int kk, int stage) {
            uint32_t s_base = sb + stage * STAGE_F + lr * 144 + lb;
            size_t goff = (size_t)lr * NT + (size_t)kk * BK;   // f32 elems
            const char* srcA = reinterpret_cast<const char*>(Ag + goff) + lb;
            const char* srcB = reinterpret_cast<const char*>(Bg + goff) + lb;
            #pragma unroll
            for (int j = 0; j < 4; j++) {
                cp16(s_base + j * 16, srcA + j * 16);
                cp16(s_base + TILE_F + j * 16, srcB + j * 16);
            }
            asm volatile("cp.async.commit_group;");
        };

        load_stage(c0, 0);
        if (c0 + 1 < c1) load_stage(c0 + 1, 1);

        for (int kk = c0; kk < c1; kk++) {
            int cur = (kk - c0) % 3;
            if (kk == c1 - 1) {
                asm volatile("cp.async.wait_group 0;" ::: "memory");
            } else {
                asm volatile("cp.async.wait_group 1;" ::: "memory");
            }
            __syncthreads();                    // stage cur ready AND old compute done
            if (kk + 2 < c1) load_stage(kk + 2, (cur + 2) % 3);

            const float* As = reinterpret_cast<const float*>(smem + cur * STAGE_F);
            const float* Bs = reinterpret_cast<const float*>(smem + cur * STAGE_F + TILE_F);

            #pragma unroll
            for (int ks = 0; ks < 4; ks++) {    // 4 x k8 steps
                wmma::fragment<wmma::matrix_a, 16, 16, 8, wmma::precision::tf32, wmma::row_major> fa[2];
                #pragma unroll
                for (int i = 0; i < 2; i++)
                    wmma::load_matrix_sync(fa[i], As + (wm * 32 + i * 16) * LDAF + ks * 8, LDAF);
                #pragma unroll
                for (int j = 0; j < 4; j++) {
                    wmma::fragment<wmma::matrix_b, 16, 16, 8, wmma::precision::tf32, wmma::col_major> fb;
                    wmma::load_matrix_sync(fb, Bs + (wn * 64 + j * 16) * LDAF + ks * 8, LDAF);
                    #pragma unroll
                    for (int i = 0; i < 2; i++)
                        wmma::mma_sync(facc[i][j], fa[i], fb, facc[i][j]);
                }
            }
        }

        __syncthreads();
        float* Es = reinterpret_cast<float*>(smem);
        #pragma unroll
        for (int i = 0; i < 2; i++)
            #pragma unroll
            for (int j = 0; j < 4; j++)
                wmma::store_matrix_sync(Es + (wm * 32 + i * 16) * LDE + wn * 64 + j * 16,
                                        facc[i][j], LDE, wmma::mem_row_major);
        __syncthreads();

        {   // write raw partial tile (gate applied in reduce)
            int r = tid >> 1;
            int ch0 = (tid & 1) * 64;
            float* Prow = g_part + (size_t)item * (BM * BN) + r * BN + ch0;
            const float* Erow = Es + r * LDE + ch0;
            #pragma unroll
            for (int q = 0; q < 16; q++)
                *reinterpret_cast<float4*>(Prow + q * 4) =
                    *reinterpret_cast<const float4*>(Erow + q * 4);
        }
        // loop-top __syncthreads orders Es reads before next item's cp.async
    }
}

// ---------------------------------------------------------------------------
// Kernel 5: reduce partials over segs, apply gate, write out.
// ---------------------------------------------------------------------------
__global__ __launch_bounds__(256) void reduce_kernel(float* __restrict__ out)
{
    int ti = blockIdx.x;
    int z  = blockIdx.y;
    int b  = z >> 1, nh = z & 1;
    int ns = (ti + 8) >> 3;
    int tid = threadIdx.x;
    int r  = tid >> 1;
    int ch = (tid & 1) * 64;
    int t  = ti * BM + r;

    int item0 = (NTILES_M - 1 - ti) * 32 + b * 8 + nh * 4;
    const float* base = g_part + (size_t)item0 * (BM * BN) + r * BN + ch;

    float4 acc[16];
    #pragma unroll
    for (int q = 0; q < 16; q++)
        acc[q] = *reinterpret_cast<const float4*>(base + q * 4);
    for (int s = 1; s < ns; s++) {
        const float* p = base + (size_t)s * (BM * BN);
        #pragma unroll
        for (int q = 0; q < 16; q++) {
            float4 v = *reinterpret_cast<const float4*>(p + q * 4);
            acc[q].x += v.x; acc[q].y += v.y; acc[q].z += v.z; acc[q].w += v.w;
        }
    }

    float rm = __uint_as_float(g_rmax[b * NT + t]);
    float f  = (rm > GATE_TH) ? 1.0f : 0.0f;
    float* Orow = out + ((size_t)b * NT + t) * ND + nh * BN + ch;
    #pragma unroll
    for (int q = 0; q < 16; q++) {
        float4 o = make_float4(acc[q].x * f, acc[q].y * f, acc[q].z * f, acc[q].w * f);
        *reinterpret_cast<float4*>(Orow + q * 4) = o;
    }
}

// ---------------------------------------------------------------------------
extern "C" void kernel_launch(void* const* d_in, const int* in_sizes, int n_in,
                              void* d_out, int out_size)
{
    const float* A = (const float*)d_in[0];   // (4, 4096, 4096) fp32
    const float* K = (const float*)d_in[1];   // (4, 4096, 256)  fp32
    float* out = (float*)d_out;               // (4, 4096, 256)  fp32

    cudaFuncSetAttribute(causal_mm_wmma, cudaFuncAttributeMaxDynamicSharedMemorySize, SM_TOTAL);

    reset_kernel<<<1, 32>>>();
    rowsum_kernel<<<NB * NT, 256>>>(A);

    dim3 gk(NT / 32, ND / 32, NB);
    kt_kernel<<<gk, 256>>>(K);

    dim3 gc(NTILES_M, NTILES_M, NB);
    convert_kernel<<<gc, 256>>>(A);

    causal_mm_wmma<<<296, 256, SM_TOTAL>>>();

    dim3 gr(NTILES_M, 8);
    reduce_kernel<<<gr, 256>>>(out);
}

// round 13
// speedup vs baseline: 1.3612x; 1.3612x over previous
#include <cuda_runtime.h>
#include <cuda_bf16.h>
#include <mma.h>
#include <math.h>
#include <stdint.h>

using namespace nvcuda;

#define NB 4
#define NT 4096
#define ND 256

#define BM 128
#define BN 128
#define BK 32
#define NTILES_M (NT / BM)      // 32
#define N_ITEMS 1024            // 32 ti * 4 b * 2 nh * 4 seg (some skipped)

#define LDA 40                  // smem row stride (bf16 elems): 32 + 8 pad = 80B
#define LDE 136                 // epilogue f32 row stride

__device__ __align__(16) float g_dinv[NB * NT];
__device__ unsigned int g_rmax[NB * NT];         // zero-init; atomicMax idempotent
__device__ int g_ctr;
__device__ __align__(16) __nv_bfloat16 g_Ahi[(size_t)NB * NT * NT];
__device__ __align__(16) __nv_bfloat16 g_Alo[(size_t)NB * NT * NT];
__device__ __align__(16) __nv_bfloat16 g_Kt_hi[(size_t)NB * ND * NT];  // [b][d][s]
__device__ __align__(16) __nv_bfloat16 g_Kt_lo[(size_t)NB * ND * NT];
__device__ __align__(16) float g_part[(size_t)N_ITEMS * BM * BN];      // 64MB partials

#define SG 0.70710678118654752440f
#define GATE_TH 7.0710678118654752e-10f          // 1e-9 * sqrt(0.5)

#define TILE_B  (128 * LDA * 2)                  // 10240
#define STAGE_B (4 * TILE_B)                     // 40960
#define SM_TOTAL (2 * STAGE_B)                   // 81920

static __device__ __forceinline__ uint32_t smem_u32(const void* p) {
    uint32_t a;
    asm("{ .reg .u64 t; cvta.to.shared.u64 t, %1; cvt.u32.u64 %0, t; }" : "=r"(a) : "l"(p));
    return a;
}
static __device__ __forceinline__ void cp16(uint32_t dst, const void* src) {
    asm volatile("cp.async.cg.shared.global [%0], [%1], 16;" :: "r"(dst), "l"(src));
}

// ---------------------------------------------------------------------------
__global__ void reset_kernel() { if (threadIdx.x == 0) g_ctr = 0; }

// ---------------------------------------------------------------------------
// Kernel 1: rowsum -> dinv   (at HBM roofline)
// ---------------------------------------------------------------------------
__global__ __launch_bounds__(256) void rowsum_kernel(const float* __restrict__ A)
{
    int row = blockIdx.x;
    const float4* a4 = reinterpret_cast<const float4*>(A + (size_t)row * NT);
    float s = 0.f;
    #pragma unroll
    for (int i = 0; i < NT / 4 / 256; i++) {
        float4 v = a4[threadIdx.x + i * 256];
        s += (v.x + v.y) + (v.z + v.w);
    }
    #pragma unroll
    for (int o = 16; o > 0; o >>= 1) s += __shfl_xor_sync(0xffffffffu, s, o);
    __shared__ float ws[8];
    int lane = threadIdx.x & 31, w = threadIdx.x >> 5;
    if (lane == 0) ws[w] = s;
    __syncthreads();
    if (threadIdx.x == 0) {
        float tot = ws[0];
        #pragma unroll
        for (int i = 1; i < 8; i++) tot += ws[i];
        g_dinv[row] = 1.0f / sqrtf(tot + 1e-6f);
    }
}

// ---------------------------------------------------------------------------
// Kernel 2: K -> Kt_hi/lo [b][d][s] bf16 split
// ---------------------------------------------------------------------------
__global__ __launch_bounds__(256) void kt_kernel(const float* __restrict__ K)
{
    __shared__ float tile[32][33];
    int s0 = blockIdx.x * 32, d0 = blockIdx.y * 32, b = blockIdx.z;
    const float* Kb = K + (size_t)b * NT * ND;
    int tid = threadIdx.x;
    #pragma unroll
    for (int q = 0; q < 4; q++) {
        int idx = tid + q * 256;
        int r = idx >> 5, c = idx & 31;
        tile[r][c] = Kb[(size_t)(s0 + r) * ND + d0 + c];
    }
    __syncthreads();
    #pragma unroll
    for (int q = 0; q < 4; q++) {
        int idx = tid + q * 256;
        int dr = idx >> 5, sc = idx & 31;
        float v = tile[sc][dr];
        __nv_bfloat16 h = __float2bfloat16(v);
        __nv_bfloat16 l = __float2bfloat16(v - __bfloat162float(h));
        size_t off = (size_t)b * ND * NT + (size_t)(d0 + dr) * NT + s0 + sc;
        g_Kt_hi[off] = h;
        g_Kt_lo[off] = l;
    }
}

// ---------------------------------------------------------------------------
// Kernel 3: convert lower-triangle A -> scaled/masked split-bf16 + rmax.
// Pair-interleaved mapping: thread (2k+h) handles elems [q*16+h*8, +8) of
// row k -> each pair's 16B stores form one contiguous 32B sector.
// ---------------------------------------------------------------------------
__global__ __launch_bounds__(256) void convert_kernel(const float* __restrict__ A)
{
    int ci = blockIdx.x, ti = blockIdx.y, b = blockIdx.z;
    if (ci > ti) return;
    int t0 = ti * 128, s0 = ci * 128;
    int tid = threadIdx.x;
    int r = tid >> 1;
    int h = tid & 1;
    int t = t0 + r;

    const float* dinv = g_dinv + b * NT;
    float dt = SG * __ldg(dinv + t);
    const float* Arow = A + (size_t)b * NT * NT + (size_t)t * NT + s0;
    __nv_bfloat16* Hdst = g_Ahi + ((size_t)b * NT + t) * NT + s0;
    __nv_bfloat16* Ldst = g_Alo + ((size_t)b * NT + t) * NT + s0;

    bool diag = (ci == ti);
    float rmax = 0.f;
    #pragma unroll
    for (int q = 0; q < 8; q++) {
        int e0 = q * 16 + h * 8;
        float4 a0 = *reinterpret_cast<const float4*>(Arow + e0);
        float4 a1 = *reinterpret_cast<const float4*>(Arow + e0 + 4);
        float4 d0 = __ldg(reinterpret_cast<const float4*>(dinv + s0 + e0));
        float4 d1 = __ldg(reinterpret_cast<const float4*>(dinv + s0 + e0 + 4));
        float v[8] = { dt * a0.x * d0.x, dt * a0.y * d0.y, dt * a0.z * d0.z, dt * a0.w * d0.w,
                       dt * a1.x * d1.x, dt * a1.y * d1.y, dt * a1.z * d1.z, dt * a1.w * d1.w };
        int sbase = s0 + e0;
        #pragma unroll
        for (int e = 0; e < 8; e++) {
            if (diag && (sbase + e > t)) v[e] = 0.f;
            rmax = fmaxf(rmax, fabsf(v[e]));
        }
        uint32_t hw[4], lw[4];
        #pragma unroll
        for (int p = 0; p < 4; p++) {
            uint32_t hp;
            asm("cvt.rn.bf16x2.f32 %0, %1, %2;"
                : "=r"(hp) : "f"(v[2 * p + 1]), "f"(v[2 * p]));
            float fe = __uint_as_float(hp << 16);
            float fo = __uint_as_float(hp & 0xffff0000u);
            uint32_t lp;
            asm("cvt.rn.bf16x2.f32 %0, %1, %2;"
                : "=r"(lp) : "f"(v[2 * p + 1] - fo), "f"(v[2 * p] - fe));
            hw[p] = hp; lw[p] = lp;
        }
        *reinterpret_cast<uint4*>(Hdst + e0) = make_uint4(hw[0], hw[1], hw[2], hw[3]);
        *reinterpret_cast<uint4*>(Ldst + e0) = make_uint4(lw[0], lw[1], lw[2], lw[3]);
    }
    rmax = fmaxf(rmax, __shfl_xor_sync(0xffffffffu, rmax, 1));
    if (h == 0)
        atomicMax(&g_rmax[b * NT + t], __float_as_uint(rmax));
}

// ---------------------------------------------------------------------------
// Kernel 4: persistent split-K WMMA GEMM. Item = (ti, b, nh, seg), seg covers
// k-chunks [32*seg, min(32*(seg+1), 4*(ti+1))). Partials (ungated) -> g_part.
// __launch_bounds__(256,2): cap regs at 128 so 2 CTAs/SM actually coresides.
// ---------------------------------------------------------------------------
__global__ __launch_bounds__(256, 2) void causal_mm_wmma()
{
    extern __shared__ char smem[];
    uint32_t sb = smem_u32(smem);
    __shared__ int s_item;

    int tid = threadIdx.x, wid = tid >> 5;
    int wm = wid & 3;
    int wn = wid >> 2;
    int lr = tid >> 1;
    int lb = (tid & 1) * 32;

    while (true) {
        if (tid == 0) s_item = atomicAdd(&g_ctr, 1);
        __syncthreads();
        int item = s_item;
        if (item >= N_ITEMS) break;

        int ti  = NTILES_M - 1 - (item >> 5);   // big tiles first
        int rem = item & 31;
        int b   = rem >> 3;
        int nh  = (rem >> 2) & 1;
        int seg = rem & 3;
        int nK  = 4 * (ti + 1);
        int ns  = (ti + 8) >> 3;                // ceil((ti+1)/8)
        if (seg >= ns) continue;
        int c0 = seg * 32;
        int c1 = min(c0 + 32, nK);

        int t0  = ti * BM;
        int cn0 = nh * BN;
        const __nv_bfloat16* AH = g_Ahi + ((size_t)b * NT + t0) * NT;
        const __nv_bfloat16* AL = g_Alo + ((size_t)b * NT + t0) * NT;
        const __nv_bfloat16* BH = g_Kt_hi + ((size_t)b * ND + cn0) * NT;
        const __nv_bfloat16* BL = g_Kt_lo + ((size_t)b * ND + cn0) * NT;

        wmma::fragment<wmma::accumulator, 16, 16, 16, float> facc[2][4];
        #pragma unroll
        for (int i = 0; i < 2; i++)
            #pragma unroll
            for (int j = 0; j < 4; j++) wmma::fill_fragment(facc[i][j], 0.0f);

        auto load_stage = [&](int kk, int stage) {
            uint32_t s_base = sb + stage * STAGE_B + lr * 80 + lb;
            size_t goff = (size_t)lr * NT + (size_t)kk * BK;
            const char* srcAH = reinterpret_cast<const char*>(AH + goff) + lb;
            const char* srcAL = reinterpret_cast<const char*>(AL + goff) + lb;
            const char* srcBH = reinterpret_cast<const char*>(BH + goff) + lb;
            const char* srcBL = reinterpret_cast<const char*>(BL + goff) + lb;
            #pragma unroll
            for (int j = 0; j < 2; j++) {
                cp16(s_base + 0 * TILE_B + j * 16, srcAH + j * 16);
                cp16(s_base + 1 * TILE_B + j * 16, srcAL + j * 16);
                cp16(s_base + 2 * TILE_B + j * 16, srcBH + j * 16);
                cp16(s_base + 3 * TILE_B + j * 16, srcBL + j * 16);
            }
            asm volatile("cp.async.commit_group;");
        };

        load_stage(c0, 0);

        for (int kk = c0; kk < c1; kk++) {
            int cur = (kk - c0) & 1;
            asm volatile("cp.async.wait_group 0;" ::: "memory");
            __syncthreads();
            if (kk + 1 < c1) load_stage(kk + 1, cur ^ 1);

            const __nv_bfloat16* AsH = reinterpret_cast<const __nv_bfloat16*>(smem + cur * STAGE_B + 0 * TILE_B);
            const __nv_bfloat16* AsL = reinterpret_cast<const __nv_bfloat16*>(smem + cur * STAGE_B + 1 * TILE_B);
            const __nv_bfloat16* BsH = reinterpret_cast<const __nv_bfloat16*>(smem + cur * STAGE_B + 2 * TILE_B);
            const __nv_bfloat16* BsL = reinterpret_cast<const __nv_bfloat16*>(smem + cur * STAGE_B + 3 * TILE_B);

            #pragma unroll
            for (int ks = 0; ks < 2; ks++) {
                wmma::fragment<wmma::matrix_a, 16, 16, 16, __nv_bfloat16, wmma::row_major> faH[2], faL[2];
                #pragma unroll
                for (int i = 0; i < 2; i++) {
                    wmma::load_matrix_sync(faH[i], AsH + (wm * 32 + i * 16) * LDA + ks * 16, LDA);
                    wmma::load_matrix_sync(faL[i], AsL + (wm * 32 + i * 16) * LDA + ks * 16, LDA);
                }
                #pragma unroll
                for (int j = 0; j < 4; j++) {
                    wmma::fragment<wmma::matrix_b, 16, 16, 16, __nv_bfloat16, wmma::col_major> fbH, fbL;
                    wmma::load_matrix_sync(fbH, BsH + (wn * 64 + j * 16) * LDA + ks * 16, LDA);
                    wmma::load_matrix_sync(fbL, BsL + (wn * 64 + j * 16) * LDA + ks * 16, LDA);
                    #pragma unroll
                    for (int i = 0; i < 2; i++) {
                        wmma::mma_sync(facc[i][j], faH[i], fbH, facc[i][j]);
                        wmma::mma_sync(facc[i][j], faH[i], fbL, facc[i][j]);
                        wmma::mma_sync(facc[i][j], faL[i], fbH, facc[i][j]);
                    }
                }
            }
        }

        __syncthreads();
        float* Es = reinterpret_cast<float*>(smem);
        #pragma unroll
        for (int i = 0; i < 2; i++)
            #pragma unroll
            for (int j = 0; j < 4; j++)
                wmma::store_matrix_sync(Es + (wm * 32 + i * 16) * LDE + wn * 64 + j * 16,
                                        facc[i][j], LDE, wmma::mem_row_major);
        __syncthreads();

        {   // write raw partial tile (gate applied in reduce)
            int r = tid >> 1;
            int ch0 = (tid & 1) * 64;
            float* Prow = g_part + (size_t)item * (BM * BN) + r * BN + ch0;
            const float* Erow = Es + r * LDE + ch0;
            #pragma unroll
            for (int q = 0; q < 16; q++)
                *reinterpret_cast<float4*>(Prow + q * 4) =
                    *reinterpret_cast<const float4*>(Erow + q * 4);
        }
        // loop-top __syncthreads orders Es reads before next item's cp.async
    }
}

// ---------------------------------------------------------------------------
// Kernel 5: reduce partials over segs, apply gate, write out.
// grid (32 ti, 8 = b*2+nh), 256 threads.
// ---------------------------------------------------------------------------
__global__ __launch_bounds__(256) void reduce_kernel(float* __restrict__ out)
{
    int ti = blockIdx.x;
    int z  = blockIdx.y;
    int b  = z >> 1, nh = z & 1;
    int ns = (ti + 8) >> 3;
    int tid = threadIdx.x;
    int r  = tid >> 1;
    int ch = (tid & 1) * 64;
    int t  = ti * BM + r;

    int item0 = (NTILES_M - 1 - ti) * 32 + b * 8 + nh * 4;
    const float* base = g_part + (size_t)item0 * (BM * BN) + r * BN + ch;

    float4 acc[16];
    #pragma unroll
    for (int q = 0; q < 16; q++)
        acc[q] = *reinterpret_cast<const float4*>(base + q * 4);
    for (int s = 1; s < ns; s++) {
        const float* p = base + (size_t)s * (BM * BN);
        #pragma unroll
        for (int q = 0; q < 16; q++) {
            float4 v = *reinterpret_cast<const float4*>(p + q * 4);
            acc[q].x += v.x; acc[q].y += v.y; acc[q].z += v.z; acc[q].w += v.w;
        }
    }

    float rm = __uint_as_float(g_rmax[b * NT + t]);
    float f  = (rm > GATE_TH) ? 1.0f : 0.0f;
    float* Orow = out + ((size_t)b * NT + t) * ND + nh * BN + ch;
    #pragma unroll
    for (int q = 0; q < 16; q++) {
        float4 o = make_float4(acc[q].x * f, acc[q].y * f, acc[q].z * f, acc[q].w * f);
        *reinterpret_cast<float4*>(Orow + q * 4) = o;
    }
}

// ---------------------------------------------------------------------------
extern "C" void kernel_launch(void* const* d_in, const int* in_sizes, int n_in,
                              void* d_out, int out_size)
{
    const float* A = (const float*)d_in[0];   // (4, 4096, 4096) fp32
    const float* K = (const float*)d_in[1];   // (4, 4096, 256)  fp32
    float* out = (float*)d_out;               // (4, 4096, 256)  fp32

    cudaFuncSetAttribute(causal_mm_wmma, cudaFuncAttributeMaxDynamicSharedMemorySize, SM_TOTAL);

    reset_kernel<<<1, 32>>>();
    rowsum_kernel<<<NB * NT, 256>>>(A);

    dim3 gk(NT / 32, ND / 32, NB);
    kt_kernel<<<gk, 256>>>(K);

    dim3 gc(NTILES_M, NTILES_M, NB);
    convert_kernel<<<gc, 256>>>(A);

    causal_mm_wmma<<<296, 256, SM_TOTAL>>>();

    dim3 gr(NTILES_M, 8);
    reduce_kernel<<<gr, 256>>>(out);
}

// round 15
// speedup vs baseline: 2.3485x; 1.7254x over previous
#include <cuda_runtime.h>
#include <cuda_fp16.h>
#include <mma.h>
#include <math.h>
#include <stdint.h>

using namespace nvcuda;

#define NB 4
#define NT 4096
#define ND 256

#define BM 128
#define BN 128
#define BK 32
#define NTILES_M (NT / BM)      // 32
#define N_ITEMS 1024            // 32 ti * 4 b * 2 nh * 4 seg (some skipped)

#define LDA 40                  // smem row stride (fp16 elems): 32 + 8 pad = 80B
#define LDE 136                 // epilogue f32 row stride

#define ASCALE 2048.0f          // 2^11: lift fp16 operands out of subnormals
#define INV_ASCALE (1.0f / 2048.0f)

__device__ __align__(16) float g_dinv[NB * NT];
__device__ unsigned int g_rmax[NB * NT];         // zero-init; atomicMax idempotent
__device__ int g_ctr;
__device__ __align__(16) __half g_Ah[(size_t)NB * NT * NT];    // SG*dinv*A*dinv*2^11, masked
__device__ __align__(16) __half g_Kth[(size_t)NB * ND * NT];   // [b][d][s]
__device__ __align__(16) float g_part[(size_t)N_ITEMS * BM * BN];  // 64MB partials

#define SG 0.70710678118654752440f
#define GATE_TH 7.0710678118654752e-10f          // 1e-9 * sqrt(0.5)

#define TILE_B  (128 * LDA * 2)                  // 10240 bytes (128 rows x 80B)
#define STAGE_B (2 * TILE_B)                     // 20480 (A + B)
#define SM_TOTAL 69632                           // epilogue needs 128*136*4; > 2 stages

static __device__ __forceinline__ uint32_t smem_u32(const void* p) {
    uint32_t a;
    asm("{ .reg .u64 t; cvta.to.shared.u64 t, %1; cvt.u32.u64 %0, t; }" : "=r"(a) : "l"(p));
    return a;
}
static __device__ __forceinline__ void cp16(uint32_t dst, const void* src) {
    asm volatile("cp.async.cg.shared.global [%0], [%1], 16;" :: "r"(dst), "l"(src));
}

// ---------------------------------------------------------------------------
__global__ void reset_kernel() { if (threadIdx.x == 0) g_ctr = 0; }

// ---------------------------------------------------------------------------
// Kernel 1: rowsum -> dinv   (at HBM roofline)
// ---------------------------------------------------------------------------
__global__ __launch_bounds__(256) void rowsum_kernel(const float* __restrict__ A)
{
    int row = blockIdx.x;
    const float4* a4 = reinterpret_cast<const float4*>(A + (size_t)row * NT);
    float s = 0.f;
    #pragma unroll
    for (int i = 0; i < NT / 4 / 256; i++) {
        float4 v = a4[threadIdx.x + i * 256];
        s += (v.x + v.y) + (v.z + v.w);
    }
    #pragma unroll
    for (int o = 16; o > 0; o >>= 1) s += __shfl_xor_sync(0xffffffffu, s, o);
    __shared__ float ws[8];
    int lane = threadIdx.x & 31, w = threadIdx.x >> 5;
    if (lane == 0) ws[w] = s;
    __syncthreads();
    if (threadIdx.x == 0) {
        float tot = ws[0];
        #pragma unroll
        for (int i = 1; i < 8; i++) tot += ws[i];
        g_dinv[row] = 1.0f / sqrtf(tot + 1e-6f);
    }
}

// ---------------------------------------------------------------------------
// Kernel 2: K[b][s][d] -> Kth[b][d][s] fp16 transpose
// ---------------------------------------------------------------------------
__global__ __launch_bounds__(256) void kt_kernel(const float* __restrict__ K)
{
    __shared__ float tile[32][33];
    int s0 = blockIdx.x * 32, d0 = blockIdx.y * 32, b = blockIdx.z;
    const float* Kb = K + (size_t)b * NT * ND;
    int tid = threadIdx.x;
    #pragma unroll
    for (int q = 0; q < 4; q++) {
        int idx = tid + q * 256;
        int r = idx >> 5, c = idx & 31;
        tile[r][c] = Kb[(size_t)(s0 + r) * ND + d0 + c];
    }
    __syncthreads();
    #pragma unroll
    for (int q = 0; q < 4; q++) {
        int idx = tid + q * 256;
        int dr = idx >> 5, sc = idx & 31;
        g_Kth[(size_t)b * ND * NT + (size_t)(d0 + dr) * NT + s0 + sc] =
            __float2half_rn(tile[sc][dr]);
    }
}

// ---------------------------------------------------------------------------
// Kernel 3: convert lower-triangle A -> scaled/masked fp16 (x2^11) + rmax.
// Pair-interleaved: thread (2k+h) handles elems [q*16+h*8, +8) of row k.
// ---------------------------------------------------------------------------
__global__ __launch_bounds__(256) void convert_kernel(const float* __restrict__ A)
{
    int ci = blockIdx.x, ti = blockIdx.y, b = blockIdx.z;
    if (ci > ti) return;
    int t0 = ti * 128, s0 = ci * 128;
    int tid = threadIdx.x;
    int r = tid >> 1;
    int h = tid & 1;
    int t = t0 + r;

    const float* dinv = g_dinv + b * NT;
    float dt = SG * __ldg(dinv + t);
    const float* Arow = A + (size_t)b * NT * NT + (size_t)t * NT + s0;
    __half* Adst = g_Ah + ((size_t)b * NT + t) * NT + s0;

    bool diag = (ci == ti);
    float rmax = 0.f;
    #pragma unroll
    for (int q = 0; q < 8; q++) {
        int e0 = q * 16 + h * 8;
        float4 a0 = *reinterpret_cast<const float4*>(Arow + e0);
        float4 a1 = *reinterpret_cast<const float4*>(Arow + e0 + 4);
        float4 d0 = __ldg(reinterpret_cast<const float4*>(dinv + s0 + e0));
        float4 d1 = __ldg(reinterpret_cast<const float4*>(dinv + s0 + e0 + 4));
        float v[8] = { dt * a0.x * d0.x, dt * a0.y * d0.y, dt * a0.z * d0.z, dt * a0.w * d0.w,
                       dt * a1.x * d1.x, dt * a1.y * d1.y, dt * a1.z * d1.z, dt * a1.w * d1.w };
        int sbase = s0 + e0;
        #pragma unroll
        for (int e = 0; e < 8; e++) {
            if (diag && (sbase + e > t)) v[e] = 0.f;
            rmax = fmaxf(rmax, fabsf(v[e]));
        }
        uint32_t hw[4];
        #pragma unroll
        for (int p = 0; p < 4; p++) {
            __half2 hp = __floats2half2_rn(v[2 * p] * ASCALE, v[2 * p + 1] * ASCALE);
            hw[p] = *reinterpret_cast<uint32_t*>(&hp);
        }
        *reinterpret_cast<uint4*>(Adst + e0) = make_uint4(hw[0], hw[1], hw[2], hw[3]);
    }
    rmax = fmaxf(rmax, __shfl_xor_sync(0xffffffffu, rmax, 1));
    if (h == 0)
        atomicMax(&g_rmax[b * NT + t], __float_as_uint(rmax));
}

// ---------------------------------------------------------------------------
// Kernel 4: persistent split-K fp16 WMMA GEMM (single term, 1/3 the MACs).
// Item = (ti, b, nh, seg); seg covers k-chunks [32*seg, min(32*(seg+1), 4*(ti+1))).
// ---------------------------------------------------------------------------
__global__ __launch_bounds__(256, 2) void causal_mm_wmma()
{
    extern __shared__ char smem[];
    uint32_t sb = smem_u32(smem);
    __shared__ int s_item;

    int tid = threadIdx.x, wid = tid >> 5;
    int wm = wid & 3;
    int wn = wid >> 2;
    int lr = tid >> 1;
    int lb = (tid & 1) * 32;

    while (true) {
        if (tid == 0) s_item = atomicAdd(&g_ctr, 1);
        __syncthreads();
        int item = s_item;
        if (item >= N_ITEMS) break;

        int ti  = NTILES_M - 1 - (item >> 5);   // big tiles first
        int rem = item & 31;
        int b   = rem >> 3;
        int nh  = (rem >> 2) & 1;
        int seg = rem & 3;
        int nK  = 4 * (ti + 1);
        int ns  = (ti + 8) >> 3;                // ceil((ti+1)/8)
        if (seg >= ns) continue;
        int c0 = seg * 32;
        int c1 = min(c0 + 32, nK);

        int t0  = ti * BM;
        int cn0 = nh * BN;
        const __half* Ag = g_Ah + ((size_t)b * NT + t0) * NT;
        const __half* Bg = g_Kth + ((size_t)b * ND + cn0) * NT;

        wmma::fragment<wmma::accumulator, 16, 16, 16, float> facc[2][4];
        #pragma unroll
        for (int i = 0; i < 2; i++)
            #pragma unroll
            for (int j = 0; j < 4; j++) wmma::fill_fragment(facc[i][j], 0.0f);

        auto load_stage = [&](int kk, int stage) {
            uint32_t s_base = sb + stage * STAGE_B + lr * 80 + lb;
            size_t goff = (size_t)lr * NT + (size_t)kk * BK;
            const char* srcA = reinterpret_cast<const char*>(Ag + goff) + lb;
            const char* srcB = reinterpret_cast<const char*>(Bg + goff) + lb;
            #pragma unroll
            for (int j = 0; j < 2; j++) {
                cp16(s_base + j * 16, srcA + j * 16);
                cp16(s_base + TILE_B + j * 16, srcB + j * 16);
            }
            asm volatile("cp.async.commit_group;");
        };

        load_stage(c0, 0);

        for (int kk = c0; kk < c1; kk++) {
            int cur = (kk - c0) & 1;
            asm volatile("cp.async.wait_group 0;" ::: "memory");
            __syncthreads();                    // stage ready AND prev compute done
            if (kk + 1 < c1) load_stage(kk + 1, cur ^ 1);

            const __half* As = reinterpret_cast<const __half*>(smem + cur * STAGE_B);
            const __half* Bs = reinterpret_cast<const __half*>(smem + cur * STAGE_B + TILE_B);

            #pragma unroll
            for (int ks = 0; ks < 2; ks++) {
                wmma::fragment<wmma::matrix_a, 16, 16, 16, __half, wmma::row_major> fa[2];
                #pragma unroll
                for (int i = 0; i < 2; i++)
                    wmma::load_matrix_sync(fa[i], As + (wm * 32 + i * 16) * LDA + ks * 16, LDA);
                #pragma unroll
                for (int j = 0; j < 4; j++) {
                    wmma::fragment<wmma::matrix_b, 16, 16, 16, __half, wmma::col_major> fb;
                    wmma::load_matrix_sync(fb, Bs + (wn * 64 + j * 16) * LDA + ks * 16, LDA);
                    #pragma unroll
                    for (int i = 0; i < 2; i++)
                        wmma::mma_sync(facc[i][j], fa[i], fb, facc[i][j]);
                }
            }
        }

        __syncthreads();
        float* Es = reinterpret_cast<float*>(smem);
        #pragma unroll
        for (int i = 0; i < 2; i++)
            #pragma unroll
            for (int j = 0; j < 4; j++)
                wmma::store_matrix_sync(Es + (wm * 32 + i * 16) * LDE + wn * 64 + j * 16,
                                        facc[i][j], LDE, wmma::mem_row_major);
        __syncthreads();

        {   // write raw partial tile (gate + descale applied in reduce)
            int r = tid >> 1;
            int ch0 = (tid & 1) * 64;
            float* Prow = g_part + (size_t)item * (BM * BN) + r * BN + ch0;
            const float* Erow = Es + r * LDE + ch0;
            #pragma unroll
            for (int q = 0; q < 16; q++)
                *reinterpret_cast<float4*>(Prow + q * 4) =
                    *reinterpret_cast<const float4*>(Erow + q * 4);
        }
        // loop-top __syncthreads orders Es reads before next item's cp.async
    }
}

// ---------------------------------------------------------------------------
// Kernel 5: reduce partials over segs, apply gate + 2^-11 descale, write out.
// ---------------------------------------------------------------------------
__global__ __launch_bounds__(256) void reduce_kernel(float* __restrict__ out)
{
    int ti = blockIdx.x;
    int z  = blockIdx.y;
    int b  = z >> 1, nh = z & 1;
    int ns = (ti + 8) >> 3;
    int tid = threadIdx.x;
    int r  = tid >> 1;
    int ch = (tid & 1) * 64;
    int t  = ti * BM + r;

    int item0 = (NTILES_M - 1 - ti) * 32 + b * 8 + nh * 4;
    const float* base = g_part + (size_t)item0 * (BM * BN) + r * BN + ch;

    float4 acc[16];
    #pragma unroll
    for (int q = 0; q < 16; q++)
        acc[q] = *reinterpret_cast<const float4*>(base + q * 4);
    for (int s = 1; s < ns; s++) {
        const float* p = base + (size_t)s * (BM * BN);
        #pragma unroll
        for (int q = 0; q < 16; q++) {
            float4 v = *reinterpret_cast<const float4*>(p + q * 4);
            acc[q].x += v.x; acc[q].y += v.y; acc[q].z += v.z; acc[q].w += v.w;
        }
    }

    float rm = __uint_as_float(g_rmax[b * NT + t]);
    float f  = (rm > GATE_TH) ? INV_ASCALE : 0.0f;
    float* Orow = out + ((size_t)b * NT + t) * ND + nh * BN + ch;
    #pragma unroll
    for (int q = 0; q < 16; q++) {
        float4 o = make_float4(acc[q].x * f, acc[q].y * f, acc[q].z * f, acc[q].w * f);
        *reinterpret_cast<float4*>(Orow + q * 4) = o;
    }
}

// ---------------------------------------------------------------------------
extern "C" void kernel_launch(void* const* d_in, const int* in_sizes, int n_in,
                              void* d_out, int out_size)
{
    const float* A = (const float*)d_in[0];   // (4, 4096, 4096) fp32
    const float* K = (const float*)d_in[1];   // (4, 4096, 256)  fp32
    float* out = (float*)d_out;               // (4, 4096, 256)  fp32

    cudaFuncSetAttribute(causal_mm_wmma, cudaFuncAttributeMaxDynamicSharedMemorySize, SM_TOTAL);

    reset_kernel<<<1, 32>>>();
    rowsum_kernel<<<NB * NT, 256>>>(A);

    dim3 gk(NT / 32, ND / 32, NB);
    kt_kernel<<<gk, 256>>>(K);

    dim3 gc(NTILES_M, NTILES_M, NB);
    convert_kernel<<<gc, 256>>>(A);

    causal_mm_wmma<<<296, 256, SM_TOTAL>>>();

    dim3 gr(NTILES_M, 8);
    reduce_kernel<<<gr, 256>>>(out);
}